// round 8
// baseline (speedup 1.0000x reference)
#include <cuda_runtime.h>
#include <cstdint>

#define B_DIM 16
#define T_DIM 8
#define C_DIM 64
#define P_DIM 2048
#define ROWS  (B_DIM * T_DIM * C_DIM)     // 8192 destination rows
#define TOTAL_ELEMS (ROWS * P_DIM)        // 16777216
#define NTHR 256
#define GRID 592                          // 148 SMs * 4 CTAs (persistent, 1 wave)
#define ROW_BYTES (P_DIM * 4)             // 8192 bytes per row
#define STAGE_BYTES (3 * ROW_BYTES)       // 24576 bytes per stage

// SMEM layout (dynamic): [0:16) mbar[2] | [16:144) shp | [256:256+48K) buffers
#define SM_OFF_MBAR 0
#define SM_OFF_SHP  16
#define SM_OFF_BUF  256
#define SMEM_TOTAL  (SM_OFF_BUF + 2 * STAGE_BYTES)

// Per-CTA partials. No device-side allocation.
__device__ float4 g_part[GRID];

__device__ __forceinline__ uint32_t smem_u32(const void* p) {
    uint32_t a;
    asm("{ .reg .u64 t; cvta.to.shared.u64 t, %1; cvt.u32.u64 %0, t; }"
        : "=r"(a) : "l"(p));
    return a;
}

__device__ __forceinline__ void mbar_wait(uint32_t mbar_a, int phase) {
    uint32_t done;
    asm volatile(
        "{\n\t.reg .pred p;\n\t"
        "mbarrier.try_wait.parity.acquire.cta.shared::cta.b64 p, [%1], %2;\n\t"
        "selp.b32 %0, 1, 0, p;\n\t}"
        : "=r"(done) : "r"(mbar_a), "r"((uint32_t)phase) : "memory");
    if (!done) {
        asm volatile(
            "{\n\t.reg .pred P1;\n\t"
            "WAIT_LOOP_%=:\n\t"
            "mbarrier.try_wait.parity.acquire.cta.shared::cta.b64 P1, [%0], %1, 0x989680;\n\t"
            "@P1 bra.uni WAIT_DONE_%=;\n\t"
            "bra.uni WAIT_LOOP_%=;\n\t"
            "WAIT_DONE_%=:\n\t}"
            :: "r"(mbar_a), "r"((uint32_t)phase) : "memory");
    }
}

__global__ __launch_bounds__(NTHR, 4) void attnloss_partial_kernel(
    const float* __restrict__ x,
    const float* __restrict__ attn,
    const float* __restrict__ noise,
    const int* __restrict__ mask,    // bool promoted to 4-byte words
    const int* __restrict__ pB1, const int* __restrict__ pT1,
    const int* __restrict__ pC1, const int* __restrict__ pP1,
    const int* __restrict__ pB2, const int* __restrict__ pT2,
    const int* __restrict__ pC2, const int* __restrict__ pP2,
    const int* __restrict__ pB3, const int* __restrict__ pT3,
    const int* __restrict__ pC3, const int* __restrict__ pP3)
{
    extern __shared__ __align__(128) char smem[];
    float* const buf = (float*)(smem + SM_OFF_BUF);      // 2 stages x 3 rows
    float4* const shp = (float4*)(smem + SM_OFF_SHP);
    const uint32_t mbar_a0 = smem_u32(smem + SM_OFF_MBAR);
    const uint32_t mbar_a1 = mbar_a0 + 8;

    const int tid = threadIdx.x;
    const int bid = blockIdx.x;

    if (tid == 0) {
        asm volatile("mbarrier.init.shared.b64 [%0], 1;" :: "r"(mbar_a0) : "memory");
        asm volatile("mbarrier.init.shared.b64 [%0], 1;" :: "r"(mbar_a1) : "memory");
    }
    __syncthreads();

    // Issue the 3 bulk row-copies for `row` into `stage`. Thread 0 only.
    auto issue = [&](int row, int stage) {
        const int c = row & (C_DIM - 1);
        const int t = (row >> 6) & (T_DIM - 1);
        const int b = row >> 9;
        const int rb1 = ((((__ldg(pB1 + b) << 3) + __ldg(pT1 + t)) << 6) + __ldg(pC1 + c)) << 11;
        const int rb2 = ((((__ldg(pB2 + b) << 3) + __ldg(pT2 + t)) << 6) + __ldg(pC2 + c)) << 11;
        const int rb3 = ((((__ldg(pB3 + b) << 3) + __ldg(pT3 + t)) << 6) + __ldg(pC3 + c)) << 11;
        const uint32_t mb = stage ? mbar_a1 : mbar_a0;
        const uint32_t d  = smem_u32(buf + stage * (3 * P_DIM));
        asm volatile("mbarrier.arrive.expect_tx.shared.b64 _, [%0], %1;"
                     :: "r"(mb), "r"((uint32_t)STAGE_BYTES) : "memory");
        asm volatile("cp.async.bulk.shared::cta.global.mbarrier::complete_tx::bytes [%0], [%1], %2, [%3];"
                     :: "r"(d), "l"(x + rb1), "r"((uint32_t)ROW_BYTES), "r"(mb) : "memory");
        asm volatile("cp.async.bulk.shared::cta.global.mbarrier::complete_tx::bytes [%0], [%1], %2, [%3];"
                     :: "r"(d + ROW_BYTES), "l"(x + rb2), "r"((uint32_t)ROW_BYTES), "r"(mb) : "memory");
        asm volatile("cp.async.bulk.shared::cta.global.mbarrier::complete_tx::bytes [%0], [%1], %2, [%3];"
                     :: "r"(d + 2 * ROW_BYTES), "l"(x + rb3), "r"((uint32_t)ROW_BYTES), "r"(mb) : "memory");
    };

    // Prologue: fill stage 0 with this CTA's first row.
    if (tid == 0 && bid < ROWS) issue(bid, 0);

    float s0 = 0.f, s1a = 0.f, s2a = 0.f, s3a = 0.f;
    int stage = 0;
    int ph0 = 0, ph1 = 0;

    for (int row = bid; row < ROWS; row += GRID) {
        const int nxt = row + GRID;
        // Prefetch next row-triple into the other stage (freed by last iter's sync).
        if (tid == 0 && nxt < ROWS) issue(nxt, stage ^ 1);

        const float* const sm1 = buf + stage * (3 * P_DIM);
        const float* const sm2 = sm1 + P_DIM;
        const float* const sm3 = sm2 + P_DIM;

        // Streaming loads for this row (coalesced, in flight across the wait).
        float4 x4[2], a4[2], n4[2];
        int4 m4[2], pp1[2], pp2[2], pp3[2];
        #pragma unroll
        for (int j = 0; j < 2; j++) {
            const int vloc = j * NTHR + tid;         // 0..511, warp-contiguous
            const int gv = (row << 9) + vloc;
            x4[j] = __ldg((const float4*)x + gv);            // L2-resident
            a4[j] = __ldcs((const float4*)attn + gv);        // stream
            n4[j] = __ldcs((const float4*)noise + gv);       // stream
            m4[j] = __ldcs((const int4*)mask + gv);          // stream
            pp1[j] = __ldg((const int4*)pP1 + vloc);         // L1-hot tables
            pp2[j] = __ldg((const int4*)pP2 + vloc);
            pp3[j] = __ldg((const int4*)pP3 + vloc);
        }

        // Wait for this stage's rows.
        if (stage == 0) { mbar_wait(mbar_a0, ph0); ph0 ^= 1; }
        else           { mbar_wait(mbar_a1, ph1); ph1 ^= 1; }

        #pragma unroll
        for (int j = 0; j < 2; j++) {
            s0 += (m4[j].x ? a4[j].x * n4[j].x * n4[j].x : 0.f)
                + (m4[j].y ? a4[j].y * n4[j].y * n4[j].y : 0.f)
                + (m4[j].z ? a4[j].z * n4[j].z * n4[j].z : 0.f)
                + (m4[j].w ? a4[j].w * n4[j].w * n4[j].w : 0.f);

            float d;
            d = x4[j].x - sm1[pp1[j].x]; s1a += a4[j].x * d * d;
            d = x4[j].y - sm1[pp1[j].y]; s1a += a4[j].y * d * d;
            d = x4[j].z - sm1[pp1[j].z]; s1a += a4[j].z * d * d;
            d = x4[j].w - sm1[pp1[j].w]; s1a += a4[j].w * d * d;

            d = x4[j].x - sm2[pp2[j].x]; s2a += a4[j].x * d * d;
            d = x4[j].y - sm2[pp2[j].y]; s2a += a4[j].y * d * d;
            d = x4[j].z - sm2[pp2[j].z]; s2a += a4[j].z * d * d;
            d = x4[j].w - sm2[pp2[j].w]; s2a += a4[j].w * d * d;

            d = x4[j].x - sm3[pp3[j].x]; s3a += a4[j].x * d * d;
            d = x4[j].y - sm3[pp3[j].y]; s3a += a4[j].y * d * d;
            d = x4[j].z - sm3[pp3[j].z]; s3a += a4[j].z * d * d;
            d = x4[j].w - sm3[pp3[j].w]; s3a += a4[j].w * d * d;
        }

        __syncthreads();      // all readers done -> this stage is free for reissue
        stage ^= 1;
    }

    // One block reduction per CTA (deterministic tree).
    #pragma unroll
    for (int o = 16; o > 0; o >>= 1) {
        s0  += __shfl_down_sync(0xffffffffu, s0,  o);
        s1a += __shfl_down_sync(0xffffffffu, s1a, o);
        s2a += __shfl_down_sync(0xffffffffu, s2a, o);
        s3a += __shfl_down_sync(0xffffffffu, s3a, o);
    }
    const int w = tid >> 5;
    if ((tid & 31) == 0) shp[w] = make_float4(s0, s1a, s2a, s3a);
    __syncthreads();

    if (tid == 0) {
        float4 acc = shp[0];
        #pragma unroll
        for (int k = 1; k < NTHR / 32; k++) {
            acc.x += shp[k].x; acc.y += shp[k].y;
            acc.z += shp[k].z; acc.w += shp[k].w;
        }
        g_part[bid] = acc;
    }
}

__global__ __launch_bounds__(NTHR) void attnloss_final_kernel(float* __restrict__ out)
{
    float4 acc = make_float4(0.f, 0.f, 0.f, 0.f);
    for (int k = threadIdx.x; k < GRID; k += NTHR) {
        const float4 p = g_part[k];
        acc.x += p.x; acc.y += p.y; acc.z += p.z; acc.w += p.w;
    }
    #pragma unroll
    for (int o = 16; o > 0; o >>= 1) {
        acc.x += __shfl_down_sync(0xffffffffu, acc.x, o);
        acc.y += __shfl_down_sync(0xffffffffu, acc.y, o);
        acc.z += __shfl_down_sync(0xffffffffu, acc.z, o);
        acc.w += __shfl_down_sync(0xffffffffu, acc.w, o);
    }
    __shared__ float4 shp[NTHR / 32];
    const int w = threadIdx.x >> 5;
    if ((threadIdx.x & 31) == 0) shp[w] = acc;
    __syncthreads();

    if (threadIdx.x == 0) {
        float4 r = shp[0];
        #pragma unroll
        for (int k = 1; k < NTHR / 32; k++) {
            r.x += shp[k].x; r.y += shp[k].y;
            r.z += shp[k].z; r.w += shp[k].w;
        }
        const float inv = 1.0f / (float)TOTAL_ELEMS;
        const float pos = r.x * inv;
        const float n1  = r.y * inv;
        const float n2  = r.z * inv;
        const float n3  = r.w * inv;
        // TEMP = 1:  loss = -pos + log(exp(n1)+exp(n2)+exp(n3))
        out[0] = -pos + logf(expf(n1) + expf(n2) + expf(n3));
    }
}

extern "C" void kernel_launch(void* const* d_in, const int* in_sizes, int n_in,
                              void* d_out, int out_size)
{
    const float* x     = (const float*)d_in[0];
    const float* attn  = (const float*)d_in[1];
    const float* noise = (const float*)d_in[2];
    const int*   mask  = (const int*)d_in[3];
    const int* pB1 = (const int*)d_in[4];
    const int* pT1 = (const int*)d_in[5];
    const int* pC1 = (const int*)d_in[6];
    const int* pP1 = (const int*)d_in[7];
    const int* pB2 = (const int*)d_in[8];
    const int* pT2 = (const int*)d_in[9];
    const int* pC2 = (const int*)d_in[10];
    const int* pP2 = (const int*)d_in[11];
    const int* pB3 = (const int*)d_in[12];
    const int* pT3 = (const int*)d_in[13];
    const int* pC3 = (const int*)d_in[14];
    const int* pP3 = (const int*)d_in[15];

    // Unconditional every call: no static guards (harness rule), idempotent,
    // deterministic. Not a stream op, so capture-safe.
    cudaFuncSetAttribute(attnloss_partial_kernel,
                         cudaFuncAttributeMaxDynamicSharedMemorySize, SMEM_TOTAL);

    attnloss_partial_kernel<<<GRID, NTHR, SMEM_TOTAL>>>(
        x, attn, noise, mask,
        pB1, pT1, pC1, pP1,
        pB2, pT2, pC2, pP2,
        pB3, pT3, pC3, pP3);
    attnloss_final_kernel<<<1, NTHR>>>((float*)d_out);
}

// round 9
// speedup vs baseline: 1.2133x; 1.2133x over previous
#include <cuda_runtime.h>
#include <cstdint>

#define B_DIM 16
#define T_DIM 8
#define C_DIM 64
#define P_DIM 2048
#define ROWS  (B_DIM * T_DIM * C_DIM)     // 8192 destination rows
#define TOTAL_ELEMS (ROWS * P_DIM)        // 16777216
#define NTHR 256
#define GRID 592                          // 148 SMs * 4 CTAs (persistent, 1 wave)
#define ROW_BYTES (P_DIM * 4)             // 8192 bytes per row
#define STAGE_BYTES (3 * ROW_BYTES)       // 24576 bytes per stage

// SMEM layout (dynamic): [0:16) mbar[2] | [16:144) shp | [256:256+48K) buffers
#define SM_OFF_MBAR 0
#define SM_OFF_SHP  16
#define SM_OFF_BUF  256
#define SMEM_TOTAL  (SM_OFF_BUF + 2 * STAGE_BYTES)

// Per-CTA partials. No device-side allocation.
__device__ float4 g_part[GRID];

__device__ __forceinline__ uint32_t smem_u32(const void* p) {
    uint32_t a;
    asm("{ .reg .u64 t; cvta.to.shared.u64 t, %1; cvt.u32.u64 %0, t; }"
        : "=r"(a) : "l"(p));
    return a;
}

__device__ __forceinline__ void mbar_wait(uint32_t mbar_a, int phase) {
    uint32_t done;
    asm volatile(
        "{\n\t.reg .pred p;\n\t"
        "mbarrier.try_wait.parity.acquire.cta.shared::cta.b64 p, [%1], %2;\n\t"
        "selp.b32 %0, 1, 0, p;\n\t}"
        : "=r"(done) : "r"(mbar_a), "r"((uint32_t)phase) : "memory");
    if (!done) {
        asm volatile(
            "{\n\t.reg .pred P1;\n\t"
            "WAIT_LOOP_%=:\n\t"
            "mbarrier.try_wait.parity.acquire.cta.shared::cta.b64 P1, [%0], %1, 0x989680;\n\t"
            "@P1 bra.uni WAIT_DONE_%=;\n\t"
            "bra.uni WAIT_LOOP_%=;\n\t"
            "WAIT_DONE_%=:\n\t}"
            :: "r"(mbar_a), "r"((uint32_t)phase) : "memory");
    }
}

// NOTE: no min-blocks clause — R8's (NTHR,4) forced a 64-reg cap onto a ~90-reg
// live set and spilled. The j-phases below are sequenced so the natural live
// set is ~50 regs; 4 CTAs/SM comes from the SMEM budget instead.
__global__ __launch_bounds__(NTHR) void attnloss_partial_kernel(
    const float* __restrict__ x,
    const float* __restrict__ attn,
    const float* __restrict__ noise,
    const int* __restrict__ mask,    // bool promoted to 4-byte words
    const int* __restrict__ pB1, const int* __restrict__ pT1,
    const int* __restrict__ pC1, const int* __restrict__ pP1,
    const int* __restrict__ pB2, const int* __restrict__ pT2,
    const int* __restrict__ pC2, const int* __restrict__ pP2,
    const int* __restrict__ pB3, const int* __restrict__ pT3,
    const int* __restrict__ pC3, const int* __restrict__ pP3)
{
    extern __shared__ __align__(128) char smem[];
    float* const buf = (float*)(smem + SM_OFF_BUF);      // 2 stages x 3 rows
    float4* const shp = (float4*)(smem + SM_OFF_SHP);
    const uint32_t mbar_a0 = smem_u32(smem + SM_OFF_MBAR);
    const uint32_t mbar_a1 = mbar_a0 + 8;

    const int tid = threadIdx.x;
    const int bid = blockIdx.x;

    if (tid == 0) {
        asm volatile("mbarrier.init.shared.b64 [%0], 1;" :: "r"(mbar_a0) : "memory");
        asm volatile("mbarrier.init.shared.b64 [%0], 1;" :: "r"(mbar_a1) : "memory");
    }
    __syncthreads();

    // Issue the 3 bulk row-copies for `row` into `stage`. Thread 0 only.
    auto issue = [&](int row, int stage) {
        const int c = row & (C_DIM - 1);
        const int t = (row >> 6) & (T_DIM - 1);
        const int b = row >> 9;
        const int rb1 = ((((__ldg(pB1 + b) << 3) + __ldg(pT1 + t)) << 6) + __ldg(pC1 + c)) << 11;
        const int rb2 = ((((__ldg(pB2 + b) << 3) + __ldg(pT2 + t)) << 6) + __ldg(pC2 + c)) << 11;
        const int rb3 = ((((__ldg(pB3 + b) << 3) + __ldg(pT3 + t)) << 6) + __ldg(pC3 + c)) << 11;
        const uint32_t mb = stage ? mbar_a1 : mbar_a0;
        const uint32_t d  = smem_u32(buf + stage * (3 * P_DIM));
        asm volatile("mbarrier.arrive.expect_tx.shared.b64 _, [%0], %1;"
                     :: "r"(mb), "r"((uint32_t)STAGE_BYTES) : "memory");
        asm volatile("cp.async.bulk.shared::cta.global.mbarrier::complete_tx::bytes [%0], [%1], %2, [%3];"
                     :: "r"(d), "l"(x + rb1), "r"((uint32_t)ROW_BYTES), "r"(mb) : "memory");
        asm volatile("cp.async.bulk.shared::cta.global.mbarrier::complete_tx::bytes [%0], [%1], %2, [%3];"
                     :: "r"(d + ROW_BYTES), "l"(x + rb2), "r"((uint32_t)ROW_BYTES), "r"(mb) : "memory");
        asm volatile("cp.async.bulk.shared::cta.global.mbarrier::complete_tx::bytes [%0], [%1], %2, [%3];"
                     :: "r"(d + 2 * ROW_BYTES), "l"(x + rb3), "r"((uint32_t)ROW_BYTES), "r"(mb) : "memory");
    };

    // Prologue: fill stage 0 with this CTA's first row.
    if (tid == 0 && bid < ROWS) issue(bid, 0);

    float s0 = 0.f, s1a = 0.f, s2a = 0.f, s3a = 0.f;
    int stage = 0;
    int ph0 = 0, ph1 = 0;

    for (int row = bid; row < ROWS; row += GRID) {
        const int nxt = row + GRID;
        // Prefetch next row-triple into the other stage (freed by last iter's sync).
        if (tid == 0 && nxt < ROWS) issue(nxt, stage ^ 1);

        const float* const sm1 = buf + stage * (3 * P_DIM);
        const float* const sm2 = sm1 + P_DIM;
        const float* const sm3 = sm2 + P_DIM;

        const int gv0 = (row << 9) + tid;            // j=0 slice
        const int gv1 = gv0 + NTHR;                  // j=1 slice

        // ---- issue long-latency loads for BOTH j-phases' pos terms, and the
        //      full j=0 gather operand set, before the wait ----
        const float4 x4_0 = __ldg((const float4*)x + gv0);        // L2-resident
        const float4 a4_0 = __ldcs((const float4*)attn + gv0);    // stream
        const float4 a4_1 = __ldcs((const float4*)attn + gv1);    // stream (kept)
        {   // consume noise/mask immediately -> dead before the wait
            const float4 n0 = __ldcs((const float4*)noise + gv0);
            const float4 n1 = __ldcs((const float4*)noise + gv1);
            const int4  m0 = __ldcs((const int4*)mask + gv0);
            const int4  m1 = __ldcs((const int4*)mask + gv1);
            s0 += (m0.x ? a4_0.x * n0.x * n0.x : 0.f)
                + (m0.y ? a4_0.y * n0.y * n0.y : 0.f)
                + (m0.z ? a4_0.z * n0.z * n0.z : 0.f)
                + (m0.w ? a4_0.w * n0.w * n0.w : 0.f);
            s0 += (m1.x ? a4_1.x * n1.x * n1.x : 0.f)
                + (m1.y ? a4_1.y * n1.y * n1.y : 0.f)
                + (m1.z ? a4_1.z * n1.z * n1.z : 0.f)
                + (m1.w ? a4_1.w * n1.w * n1.w : 0.f);
        }
        const int4 p1_0 = __ldg((const int4*)pP1 + tid);          // L1-hot
        const int4 p2_0 = __ldg((const int4*)pP2 + tid);
        const int4 p3_0 = __ldg((const int4*)pP3 + tid);

        // ---- wait for this stage's rows ----
        if (stage == 0) { mbar_wait(mbar_a0, ph0); ph0 ^= 1; }
        else           { mbar_wait(mbar_a1, ph1); ph1 ^= 1; }

        // ---- j=0 gather/accumulate ----
        {
            float d;
            d = x4_0.x - sm1[p1_0.x]; s1a += a4_0.x * d * d;
            d = x4_0.y - sm1[p1_0.y]; s1a += a4_0.y * d * d;
            d = x4_0.z - sm1[p1_0.z]; s1a += a4_0.z * d * d;
            d = x4_0.w - sm1[p1_0.w]; s1a += a4_0.w * d * d;

            d = x4_0.x - sm2[p2_0.x]; s2a += a4_0.x * d * d;
            d = x4_0.y - sm2[p2_0.y]; s2a += a4_0.y * d * d;
            d = x4_0.z - sm2[p2_0.z]; s2a += a4_0.z * d * d;
            d = x4_0.w - sm2[p2_0.w]; s2a += a4_0.w * d * d;

            d = x4_0.x - sm3[p3_0.x]; s3a += a4_0.x * d * d;
            d = x4_0.y - sm3[p3_0.y]; s3a += a4_0.y * d * d;
            d = x4_0.z - sm3[p3_0.z]; s3a += a4_0.z * d * d;
            d = x4_0.w - sm3[p3_0.w]; s3a += a4_0.w * d * d;
        }

        // ---- j=1: short-latency operands (L1/L2 hits), then gather ----
        {
            const float4 x4_1 = __ldg((const float4*)x + gv1);
            const int4 p1_1 = __ldg((const int4*)pP1 + NTHR + tid);
            const int4 p2_1 = __ldg((const int4*)pP2 + NTHR + tid);
            const int4 p3_1 = __ldg((const int4*)pP3 + NTHR + tid);

            float d;
            d = x4_1.x - sm1[p1_1.x]; s1a += a4_1.x * d * d;
            d = x4_1.y - sm1[p1_1.y]; s1a += a4_1.y * d * d;
            d = x4_1.z - sm1[p1_1.z]; s1a += a4_1.z * d * d;
            d = x4_1.w - sm1[p1_1.w]; s1a += a4_1.w * d * d;

            d = x4_1.x - sm2[p2_1.x]; s2a += a4_1.x * d * d;
            d = x4_1.y - sm2[p2_1.y]; s2a += a4_1.y * d * d;
            d = x4_1.z - sm2[p2_1.z]; s2a += a4_1.z * d * d;
            d = x4_1.w - sm2[p2_1.w]; s2a += a4_1.w * d * d;

            d = x4_1.x - sm3[p3_1.x]; s3a += a4_1.x * d * d;
            d = x4_1.y - sm3[p3_1.y]; s3a += a4_1.y * d * d;
            d = x4_1.z - sm3[p3_1.z]; s3a += a4_1.z * d * d;
            d = x4_1.w - sm3[p3_1.w]; s3a += a4_1.w * d * d;
        }

        __syncthreads();      // all readers done -> this stage is free for reissue
        stage ^= 1;
    }

    // One block reduction per CTA (deterministic tree).
    #pragma unroll
    for (int o = 16; o > 0; o >>= 1) {
        s0  += __shfl_down_sync(0xffffffffu, s0,  o);
        s1a += __shfl_down_sync(0xffffffffu, s1a, o);
        s2a += __shfl_down_sync(0xffffffffu, s2a, o);
        s3a += __shfl_down_sync(0xffffffffu, s3a, o);
    }
    const int w = tid >> 5;
    if ((tid & 31) == 0) shp[w] = make_float4(s0, s1a, s2a, s3a);
    __syncthreads();

    if (tid == 0) {
        float4 acc = shp[0];
        #pragma unroll
        for (int k = 1; k < NTHR / 32; k++) {
            acc.x += shp[k].x; acc.y += shp[k].y;
            acc.z += shp[k].z; acc.w += shp[k].w;
        }
        g_part[bid] = acc;
    }
}

__global__ __launch_bounds__(NTHR) void attnloss_final_kernel(float* __restrict__ out)
{
    float4 acc = make_float4(0.f, 0.f, 0.f, 0.f);
    for (int k = threadIdx.x; k < GRID; k += NTHR) {
        const float4 p = g_part[k];
        acc.x += p.x; acc.y += p.y; acc.z += p.z; acc.w += p.w;
    }
    #pragma unroll
    for (int o = 16; o > 0; o >>= 1) {
        acc.x += __shfl_down_sync(0xffffffffu, acc.x, o);
        acc.y += __shfl_down_sync(0xffffffffu, acc.y, o);
        acc.z += __shfl_down_sync(0xffffffffu, acc.z, o);
        acc.w += __shfl_down_sync(0xffffffffu, acc.w, o);
    }
    __shared__ float4 shp[NTHR / 32];
    const int w = threadIdx.x >> 5;
    if ((threadIdx.x & 31) == 0) shp[w] = acc;
    __syncthreads();

    if (threadIdx.x == 0) {
        float4 r = shp[0];
        #pragma unroll
        for (int k = 1; k < NTHR / 32; k++) {
            r.x += shp[k].x; r.y += shp[k].y;
            r.z += shp[k].z; r.w += shp[k].w;
        }
        const float inv = 1.0f / (float)TOTAL_ELEMS;
        const float pos = r.x * inv;
        const float n1  = r.y * inv;
        const float n2  = r.z * inv;
        const float n3  = r.w * inv;
        // TEMP = 1:  loss = -pos + log(exp(n1)+exp(n2)+exp(n3))
        out[0] = -pos + logf(expf(n1) + expf(n2) + expf(n3));
    }
}

extern "C" void kernel_launch(void* const* d_in, const int* in_sizes, int n_in,
                              void* d_out, int out_size)
{
    const float* x     = (const float*)d_in[0];
    const float* attn  = (const float*)d_in[1];
    const float* noise = (const float*)d_in[2];
    const int*   mask  = (const int*)d_in[3];
    const int* pB1 = (const int*)d_in[4];
    const int* pT1 = (const int*)d_in[5];
    const int* pC1 = (const int*)d_in[6];
    const int* pP1 = (const int*)d_in[7];
    const int* pB2 = (const int*)d_in[8];
    const int* pT2 = (const int*)d_in[9];
    const int* pC2 = (const int*)d_in[10];
    const int* pP2 = (const int*)d_in[11];
    const int* pB3 = (const int*)d_in[12];
    const int* pT3 = (const int*)d_in[13];
    const int* pC3 = (const int*)d_in[14];
    const int* pP3 = (const int*)d_in[15];

    // Unconditional every call: no static guards (harness rule), idempotent,
    // deterministic. Not a stream op, so capture-safe.
    cudaFuncSetAttribute(attnloss_partial_kernel,
                         cudaFuncAttributeMaxDynamicSharedMemorySize, SMEM_TOTAL);

    attnloss_partial_kernel<<<GRID, NTHR, SMEM_TOTAL>>>(
        x, attn, noise, mask,
        pB1, pT1, pC1, pP1,
        pB2, pT2, pC2, pP2,
        pB3, pT3, pC3, pP3);
    attnloss_final_kernel<<<1, NTHR>>>((float*)d_out);
}

// round 10
// speedup vs baseline: 1.3352x; 1.1005x over previous
#include <cuda_runtime.h>
#include <cstdint>

#define B_DIM 16
#define T_DIM 8
#define C_DIM 64
#define P_DIM 2048
#define ROWS  (B_DIM * T_DIM * C_DIM)     // 8192 destination rows
#define TOTAL_ELEMS (ROWS * P_DIM)        // 16777216
#define NTHR 256
#define ROW_BYTES (P_DIM * 4)             // 8192 bytes per row

// Block partials (float4 per destination row). No device-side allocation.
__device__ float4 g_part[ROWS];

__device__ __forceinline__ uint32_t smem_u32(const void* p) {
    uint32_t a;
    asm("{ .reg .u64 t; cvta.to.shared.u64 t, %1; cvt.u32.u64 %0, t; }"
        : "=r"(a) : "l"(p));
    return a;
}

// One CTA per destination row. Independent CTAs at different pipeline phases
// give the SM natural TMA/compute overlap (beat the lockstep persistent
// variant by 8+ us in R8/R9). Live set kept ~52 regs via sequential j-phases
// -> ~5 CTAs/SM resident.
__global__ __launch_bounds__(NTHR) void attnloss_partial_kernel(
    const float* __restrict__ x,
    const float* __restrict__ attn,
    const float* __restrict__ noise,
    const int* __restrict__ mask,    // bool promoted to 4-byte words
    const int* __restrict__ pB1, const int* __restrict__ pT1,
    const int* __restrict__ pC1, const int* __restrict__ pP1,
    const int* __restrict__ pB2, const int* __restrict__ pT2,
    const int* __restrict__ pC2, const int* __restrict__ pP2,
    const int* __restrict__ pB3, const int* __restrict__ pT3,
    const int* __restrict__ pC3, const int* __restrict__ pP3)
{
    __shared__ __align__(128) float sm[3 * P_DIM];   // 24 KB: three source rows
    __shared__ __align__(8) uint64_t mbar;

    const float* const sm1 = sm;
    const float* const sm2 = sm + P_DIM;
    const float* const sm3 = sm + 2 * P_DIM;

    const int tid = threadIdx.x;
    const int blk = blockIdx.x;              // destination row id
    const uint32_t mbar_a = smem_u32(&mbar);

    if (tid == 0) {
        asm volatile("mbarrier.init.shared.b64 [%0], 1;" :: "r"(mbar_a) : "memory");
    }
    __syncthreads();

    if (tid == 0) {
        const int c = blk & (C_DIM - 1);
        const int t = (blk >> 6) & (T_DIM - 1);
        const int b = blk >> 9;
        // Source row bases (contiguous 8 KB rows of x). 32-bit math: max < 2^24.
        const int rb1 = ((((__ldg(pB1 + b) << 3) + __ldg(pT1 + t)) << 6) + __ldg(pC1 + c)) << 11;
        const int rb2 = ((((__ldg(pB2 + b) << 3) + __ldg(pT2 + t)) << 6) + __ldg(pC2 + c)) << 11;
        const int rb3 = ((((__ldg(pB3 + b) << 3) + __ldg(pT3 + t)) << 6) + __ldg(pC3 + c)) << 11;

        asm volatile("mbarrier.arrive.expect_tx.shared.b64 _, [%0], %1;"
                     :: "r"(mbar_a), "r"(3 * ROW_BYTES) : "memory");
        asm volatile("cp.async.bulk.shared::cta.global.mbarrier::complete_tx::bytes [%0], [%1], %2, [%3];"
                     :: "r"(smem_u32(sm1)), "l"(x + rb1), "r"(ROW_BYTES), "r"(mbar_a) : "memory");
        asm volatile("cp.async.bulk.shared::cta.global.mbarrier::complete_tx::bytes [%0], [%1], %2, [%3];"
                     :: "r"(smem_u32(sm2)), "l"(x + rb2), "r"(ROW_BYTES), "r"(mbar_a) : "memory");
        asm volatile("cp.async.bulk.shared::cta.global.mbarrier::complete_tx::bytes [%0], [%1], %2, [%3];"
                     :: "r"(smem_u32(sm3)), "l"(x + rb3), "r"(ROW_BYTES), "r"(mbar_a) : "memory");
    }

    float s0 = 0.f, s1a = 0.f, s2a = 0.f, s3a = 0.f;

    const int gv0 = (blk << 9) + tid;            // j=0 slice (warp-contiguous)
    const int gv1 = gv0 + NTHR;                  // j=1 slice

    // ---- long-latency streaming loads, pos terms consumed immediately ----
    const float4 x4_0 = __ldg((const float4*)x + gv0);        // L2-resident
    const float4 a4_0 = __ldcs((const float4*)attn + gv0);    // stream
    const float4 a4_1 = __ldcs((const float4*)attn + gv1);    // stream (kept)
    {   // noise/mask dead before the wait -> small live set across it
        const float4 n0 = __ldcs((const float4*)noise + gv0);
        const float4 n1 = __ldcs((const float4*)noise + gv1);
        const int4  m0 = __ldcs((const int4*)mask + gv0);
        const int4  m1 = __ldcs((const int4*)mask + gv1);
        s0 += (m0.x ? a4_0.x * n0.x * n0.x : 0.f)
            + (m0.y ? a4_0.y * n0.y * n0.y : 0.f)
            + (m0.z ? a4_0.z * n0.z * n0.z : 0.f)
            + (m0.w ? a4_0.w * n0.w * n0.w : 0.f);
        s0 += (m1.x ? a4_1.x * n1.x * n1.x : 0.f)
            + (m1.y ? a4_1.y * n1.y * n1.y : 0.f)
            + (m1.z ? a4_1.z * n1.z * n1.z : 0.f)
            + (m1.w ? a4_1.w * n1.w * n1.w : 0.f);
    }
    const int4 p1_0 = __ldg((const int4*)pP1 + tid);          // L1-hot tables
    const int4 p2_0 = __ldg((const int4*)pP2 + tid);
    const int4 p3_0 = __ldg((const int4*)pP3 + tid);

    // ---- wait for the three source rows ----
    {
        uint32_t done;
        asm volatile(
            "{\n\t.reg .pred p;\n\t"
            "mbarrier.try_wait.parity.acquire.cta.shared::cta.b64 p, [%1], 0;\n\t"
            "selp.b32 %0, 1, 0, p;\n\t}"
            : "=r"(done) : "r"(mbar_a) : "memory");
        if (!done) {
            asm volatile(
                "{\n\t.reg .pred P1;\n\t"
                "WAIT_LOOP_%=:\n\t"
                "mbarrier.try_wait.parity.acquire.cta.shared::cta.b64 P1, [%0], 0, 0x989680;\n\t"
                "@P1 bra.uni WAIT_DONE_%=;\n\t"
                "bra.uni WAIT_LOOP_%=;\n\t"
                "WAIT_DONE_%=:\n\t}"
                :: "r"(mbar_a) : "memory");
        }
    }

    // ---- j=0 gather/accumulate ----
    {
        float d;
        d = x4_0.x - sm1[p1_0.x]; s1a += a4_0.x * d * d;
        d = x4_0.y - sm1[p1_0.y]; s1a += a4_0.y * d * d;
        d = x4_0.z - sm1[p1_0.z]; s1a += a4_0.z * d * d;
        d = x4_0.w - sm1[p1_0.w]; s1a += a4_0.w * d * d;

        d = x4_0.x - sm2[p2_0.x]; s2a += a4_0.x * d * d;
        d = x4_0.y - sm2[p2_0.y]; s2a += a4_0.y * d * d;
        d = x4_0.z - sm2[p2_0.z]; s2a += a4_0.z * d * d;
        d = x4_0.w - sm2[p2_0.w]; s2a += a4_0.w * d * d;

        d = x4_0.x - sm3[p3_0.x]; s3a += a4_0.x * d * d;
        d = x4_0.y - sm3[p3_0.y]; s3a += a4_0.y * d * d;
        d = x4_0.z - sm3[p3_0.z]; s3a += a4_0.z * d * d;
        d = x4_0.w - sm3[p3_0.w]; s3a += a4_0.w * d * d;
    }

    // ---- j=1: short-latency operands (L1/L2 hits), then gather ----
    {
        const float4 x4_1 = __ldg((const float4*)x + gv1);
        const int4 p1_1 = __ldg((const int4*)pP1 + NTHR + tid);
        const int4 p2_1 = __ldg((const int4*)pP2 + NTHR + tid);
        const int4 p3_1 = __ldg((const int4*)pP3 + NTHR + tid);

        float d;
        d = x4_1.x - sm1[p1_1.x]; s1a += a4_1.x * d * d;
        d = x4_1.y - sm1[p1_1.y]; s1a += a4_1.y * d * d;
        d = x4_1.z - sm1[p1_1.z]; s1a += a4_1.z * d * d;
        d = x4_1.w - sm1[p1_1.w]; s1a += a4_1.w * d * d;

        d = x4_1.x - sm2[p2_1.x]; s2a += a4_1.x * d * d;
        d = x4_1.y - sm2[p2_1.y]; s2a += a4_1.y * d * d;
        d = x4_1.z - sm2[p2_1.z]; s2a += a4_1.z * d * d;
        d = x4_1.w - sm2[p2_1.w]; s2a += a4_1.w * d * d;

        d = x4_1.x - sm3[p3_1.x]; s3a += a4_1.x * d * d;
        d = x4_1.y - sm3[p3_1.y]; s3a += a4_1.y * d * d;
        d = x4_1.z - sm3[p3_1.z]; s3a += a4_1.z * d * d;
        d = x4_1.w - sm3[p3_1.w]; s3a += a4_1.w * d * d;
    }

    // Block reduction (deterministic tree)
    #pragma unroll
    for (int o = 16; o > 0; o >>= 1) {
        s0  += __shfl_down_sync(0xffffffffu, s0,  o);
        s1a += __shfl_down_sync(0xffffffffu, s1a, o);
        s2a += __shfl_down_sync(0xffffffffu, s2a, o);
        s3a += __shfl_down_sync(0xffffffffu, s3a, o);
    }
    __shared__ float4 shp[NTHR / 32];
    const int w = tid >> 5;
    if ((tid & 31) == 0) shp[w] = make_float4(s0, s1a, s2a, s3a);
    __syncthreads();

    if (tid == 0) {
        float4 acc = shp[0];
        #pragma unroll
        for (int k = 1; k < NTHR / 32; k++) {
            acc.x += shp[k].x; acc.y += shp[k].y;
            acc.z += shp[k].z; acc.w += shp[k].w;
        }
        g_part[blk] = acc;
    }
}

#define FTHR 1024

__global__ __launch_bounds__(FTHR) void attnloss_final_kernel(float* __restrict__ out)
{
    float4 acc = make_float4(0.f, 0.f, 0.f, 0.f);
    // 8192 partials / 1024 threads = 8 each; fully unrolled for MLP.
    #pragma unroll
    for (int u = 0; u < ROWS / FTHR; u++) {
        const float4 p = g_part[u * FTHR + threadIdx.x];
        acc.x += p.x; acc.y += p.y; acc.z += p.z; acc.w += p.w;
    }
    #pragma unroll
    for (int o = 16; o > 0; o >>= 1) {
        acc.x += __shfl_down_sync(0xffffffffu, acc.x, o);
        acc.y += __shfl_down_sync(0xffffffffu, acc.y, o);
        acc.z += __shfl_down_sync(0xffffffffu, acc.z, o);
        acc.w += __shfl_down_sync(0xffffffffu, acc.w, o);
    }
    __shared__ float4 shp[FTHR / 32];
    const int w = threadIdx.x >> 5;
    if ((threadIdx.x & 31) == 0) shp[w] = acc;
    __syncthreads();

    if (threadIdx.x == 0) {
        float4 r = shp[0];
        #pragma unroll
        for (int k = 1; k < FTHR / 32; k++) {
            r.x += shp[k].x; r.y += shp[k].y;
            r.z += shp[k].z; r.w += shp[k].w;
        }
        const float inv = 1.0f / (float)TOTAL_ELEMS;
        const float pos = r.x * inv;
        const float n1  = r.y * inv;
        const float n2  = r.z * inv;
        const float n3  = r.w * inv;
        // TEMP = 1:  loss = -pos + log(exp(n1)+exp(n2)+exp(n3))
        out[0] = -pos + logf(expf(n1) + expf(n2) + expf(n3));
    }
}

extern "C" void kernel_launch(void* const* d_in, const int* in_sizes, int n_in,
                              void* d_out, int out_size)
{
    const float* x     = (const float*)d_in[0];
    const float* attn  = (const float*)d_in[1];
    const float* noise = (const float*)d_in[2];
    const int*   mask  = (const int*)d_in[3];
    const int* pB1 = (const int*)d_in[4];
    const int* pT1 = (const int*)d_in[5];
    const int* pC1 = (const int*)d_in[6];
    const int* pP1 = (const int*)d_in[7];
    const int* pB2 = (const int*)d_in[8];
    const int* pT2 = (const int*)d_in[9];
    const int* pC2 = (const int*)d_in[10];
    const int* pP2 = (const int*)d_in[11];
    const int* pB3 = (const int*)d_in[12];
    const int* pT3 = (const int*)d_in[13];
    const int* pC3 = (const int*)d_in[14];
    const int* pP3 = (const int*)d_in[15];

    attnloss_partial_kernel<<<ROWS, NTHR>>>(
        x, attn, noise, mask,
        pB1, pT1, pC1, pP1,
        pB2, pT2, pC2, pP2,
        pB3, pT3, pC3, pP3);
    attnloss_final_kernel<<<1, FTHR>>>((float*)d_out);
}

// round 11
// speedup vs baseline: 1.3422x; 1.0052x over previous
#include <cuda_runtime.h>
#include <cstdint>

#define B_DIM 16
#define T_DIM 8
#define C_DIM 64
#define P_DIM 2048
#define ROWS  (B_DIM * T_DIM * C_DIM)     // 8192 destination rows
#define TOTAL_ELEMS (ROWS * P_DIM)        // 16777216
#define NTHR 256
#define ROW_BYTES (P_DIM * 4)             // 8192 bytes per row

// Block partials (float4 per destination row). No device-side allocation.
__device__ float4 g_part[ROWS];

__device__ __forceinline__ uint32_t smem_u32(const void* p) {
    uint32_t a;
    asm("{ .reg .u64 t; cvta.to.shared.u64 t, %1; cvt.u32.u64 %0, t; }"
        : "=r"(a) : "l"(p));
    return a;
}

// Empty pacing kernel: shifts the ncu -s 5 -c 1 capture window so launch
// index 5 is the PARTIAL kernel (sequence per call: D,P,F,D -> idx5 = P).
__global__ void attnloss_pace_kernel() {}

// R6 structure (best measured main kernel: ~52.8us): one CTA per destination
// row, TMA row-fill, ALL loads batched up front for max MLP.
__global__ __launch_bounds__(NTHR) void attnloss_partial_kernel(
    const float* __restrict__ x,
    const float* __restrict__ attn,
    const float* __restrict__ noise,
    const int* __restrict__ mask,    // bool promoted to 4-byte words
    const int* __restrict__ pB1, const int* __restrict__ pT1,
    const int* __restrict__ pC1, const int* __restrict__ pP1,
    const int* __restrict__ pB2, const int* __restrict__ pT2,
    const int* __restrict__ pC2, const int* __restrict__ pP2,
    const int* __restrict__ pB3, const int* __restrict__ pT3,
    const int* __restrict__ pC3, const int* __restrict__ pP3)
{
    __shared__ __align__(128) float sm[3 * P_DIM];   // 24 KB: three source rows
    __shared__ __align__(8) uint64_t mbar;

    const float* const sm1 = sm;
    const float* const sm2 = sm + P_DIM;
    const float* const sm3 = sm + 2 * P_DIM;

    const int tid = threadIdx.x;
    const int blk = blockIdx.x;              // destination row id
    const uint32_t mbar_a = smem_u32(&mbar);

    if (tid == 0) {
        asm volatile("mbarrier.init.shared.b64 [%0], 1;" :: "r"(mbar_a) : "memory");
    }
    __syncthreads();

    if (tid == 0) {
        const int c = blk & (C_DIM - 1);
        const int t = (blk >> 6) & (T_DIM - 1);
        const int b = blk >> 9;
        // Source row bases (contiguous 8 KB rows of x). 32-bit math: max < 2^24.
        const int rb1 = ((((__ldg(pB1 + b) << 3) + __ldg(pT1 + t)) << 6) + __ldg(pC1 + c)) << 11;
        const int rb2 = ((((__ldg(pB2 + b) << 3) + __ldg(pT2 + t)) << 6) + __ldg(pC2 + c)) << 11;
        const int rb3 = ((((__ldg(pB3 + b) << 3) + __ldg(pT3 + t)) << 6) + __ldg(pC3 + c)) << 11;

        asm volatile("mbarrier.arrive.expect_tx.shared.b64 _, [%0], %1;"
                     :: "r"(mbar_a), "r"(3 * ROW_BYTES) : "memory");
        asm volatile("cp.async.bulk.shared::cta.global.mbarrier::complete_tx::bytes [%0], [%1], %2, [%3];"
                     :: "r"(smem_u32(sm1)), "l"(x + rb1), "r"(ROW_BYTES), "r"(mbar_a) : "memory");
        asm volatile("cp.async.bulk.shared::cta.global.mbarrier::complete_tx::bytes [%0], [%1], %2, [%3];"
                     :: "r"(smem_u32(sm2)), "l"(x + rb2), "r"(ROW_BYTES), "r"(mbar_a) : "memory");
        asm volatile("cp.async.bulk.shared::cta.global.mbarrier::complete_tx::bytes [%0], [%1], %2, [%3];"
                     :: "r"(smem_u32(sm3)), "l"(x + rb3), "r"(ROW_BYTES), "r"(mbar_a) : "memory");
    }

    // Batch ALL streaming loads up front (max MLP, in flight across the wait).
    float4 x4[2], a4[2], n4[2];
    int4 m4[2], pp1[2], pp2[2], pp3[2];
    #pragma unroll
    for (int j = 0; j < 2; j++) {
        const int vloc = j * NTHR + tid;         // 0..511, warp-contiguous
        const int gv = (blk << 9) + vloc;
        x4[j] = __ldg((const float4*)x + gv);            // L2-resident
        a4[j] = __ldcs((const float4*)attn + gv);        // stream
        n4[j] = __ldcs((const float4*)noise + gv);       // stream
        m4[j] = __ldcs((const int4*)mask + gv);          // stream
        pp1[j] = __ldg((const int4*)pP1 + vloc);         // L1-hot tables
        pp2[j] = __ldg((const int4*)pP2 + vloc);
        pp3[j] = __ldg((const int4*)pP3 + vloc);
    }

    // Wait for the three source rows (acquire orders the LDS gathers below).
    {
        uint32_t done;
        asm volatile(
            "{\n\t.reg .pred p;\n\t"
            "mbarrier.try_wait.parity.acquire.cta.shared::cta.b64 p, [%1], 0;\n\t"
            "selp.b32 %0, 1, 0, p;\n\t}"
            : "=r"(done) : "r"(mbar_a) : "memory");
        if (!done) {
            asm volatile(
                "{\n\t.reg .pred P1;\n\t"
                "WAIT_LOOP_%=:\n\t"
                "mbarrier.try_wait.parity.acquire.cta.shared::cta.b64 P1, [%0], 0, 0x989680;\n\t"
                "@P1 bra.uni WAIT_DONE_%=;\n\t"
                "bra.uni WAIT_LOOP_%=;\n\t"
                "WAIT_DONE_%=:\n\t}"
                :: "r"(mbar_a) : "memory");
        }
    }

    float s0 = 0.f, s1a = 0.f, s2a = 0.f, s3a = 0.f;

    #pragma unroll
    for (int j = 0; j < 2; j++) {
        s0 += (m4[j].x ? a4[j].x * n4[j].x * n4[j].x : 0.f)
            + (m4[j].y ? a4[j].y * n4[j].y * n4[j].y : 0.f)
            + (m4[j].z ? a4[j].z * n4[j].z * n4[j].z : 0.f)
            + (m4[j].w ? a4[j].w * n4[j].w * n4[j].w : 0.f);

        float d;
        d = x4[j].x - sm1[pp1[j].x]; s1a += a4[j].x * d * d;
        d = x4[j].y - sm1[pp1[j].y]; s1a += a4[j].y * d * d;
        d = x4[j].z - sm1[pp1[j].z]; s1a += a4[j].z * d * d;
        d = x4[j].w - sm1[pp1[j].w]; s1a += a4[j].w * d * d;

        d = x4[j].x - sm2[pp2[j].x]; s2a += a4[j].x * d * d;
        d = x4[j].y - sm2[pp2[j].y]; s2a += a4[j].y * d * d;
        d = x4[j].z - sm2[pp2[j].z]; s2a += a4[j].z * d * d;
        d = x4[j].w - sm2[pp2[j].w]; s2a += a4[j].w * d * d;

        d = x4[j].x - sm3[pp3[j].x]; s3a += a4[j].x * d * d;
        d = x4[j].y - sm3[pp3[j].y]; s3a += a4[j].y * d * d;
        d = x4[j].z - sm3[pp3[j].z]; s3a += a4[j].z * d * d;
        d = x4[j].w - sm3[pp3[j].w]; s3a += a4[j].w * d * d;
    }

    // Block reduction (deterministic tree)
    #pragma unroll
    for (int o = 16; o > 0; o >>= 1) {
        s0  += __shfl_down_sync(0xffffffffu, s0,  o);
        s1a += __shfl_down_sync(0xffffffffu, s1a, o);
        s2a += __shfl_down_sync(0xffffffffu, s2a, o);
        s3a += __shfl_down_sync(0xffffffffu, s3a, o);
    }
    __shared__ float4 shp[NTHR / 32];
    const int w = tid >> 5;
    if ((tid & 31) == 0) shp[w] = make_float4(s0, s1a, s2a, s3a);
    __syncthreads();

    if (tid == 0) {
        float4 acc = shp[0];
        #pragma unroll
        for (int k = 1; k < NTHR / 32; k++) {
            acc.x += shp[k].x; acc.y += shp[k].y;
            acc.z += shp[k].z; acc.w += shp[k].w;
        }
        g_part[blk] = acc;
    }
}

#define FTHR 1024

__global__ __launch_bounds__(FTHR) void attnloss_final_kernel(float* __restrict__ out)
{
    float4 acc = make_float4(0.f, 0.f, 0.f, 0.f);
    #pragma unroll
    for (int u = 0; u < ROWS / FTHR; u++) {
        const float4 p = g_part[u * FTHR + threadIdx.x];
        acc.x += p.x; acc.y += p.y; acc.z += p.z; acc.w += p.w;
    }
    #pragma unroll
    for (int o = 16; o > 0; o >>= 1) {
        acc.x += __shfl_down_sync(0xffffffffu, acc.x, o);
        acc.y += __shfl_down_sync(0xffffffffu, acc.y, o);
        acc.z += __shfl_down_sync(0xffffffffu, acc.z, o);
        acc.w += __shfl_down_sync(0xffffffffu, acc.w, o);
    }
    __shared__ float4 shp[FTHR / 32];
    const int w = threadIdx.x >> 5;
    if ((threadIdx.x & 31) == 0) shp[w] = acc;
    __syncthreads();

    if (threadIdx.x == 0) {
        float4 r = shp[0];
        #pragma unroll
        for (int k = 1; k < FTHR / 32; k++) {
            r.x += shp[k].x; r.y += shp[k].y;
            r.z += shp[k].z; r.w += shp[k].w;
        }
        const float inv = 1.0f / (float)TOTAL_ELEMS;
        const float pos = r.x * inv;
        const float n1  = r.y * inv;
        const float n2  = r.z * inv;
        const float n3  = r.w * inv;
        // TEMP = 1:  loss = -pos + log(exp(n1)+exp(n2)+exp(n3))
        out[0] = -pos + logf(expf(n1) + expf(n2) + expf(n3));
    }
}

extern "C" void kernel_launch(void* const* d_in, const int* in_sizes, int n_in,
                              void* d_out, int out_size)
{
    const float* x     = (const float*)d_in[0];
    const float* attn  = (const float*)d_in[1];
    const float* noise = (const float*)d_in[2];
    const int*   mask  = (const int*)d_in[3];
    const int* pB1 = (const int*)d_in[4];
    const int* pT1 = (const int*)d_in[5];
    const int* pC1 = (const int*)d_in[6];
    const int* pP1 = (const int*)d_in[7];
    const int* pB2 = (const int*)d_in[8];
    const int* pT2 = (const int*)d_in[9];
    const int* pC2 = (const int*)d_in[10];
    const int* pP2 = (const int*)d_in[11];
    const int* pB3 = (const int*)d_in[12];
    const int* pT3 = (const int*)d_in[13];
    const int* pC3 = (const int*)d_in[14];
    const int* pP3 = (const int*)d_in[15];

    // Launch sequence D,P,F,D: makes global launch index 5 (ncu -s 5 -c 1)
    // land on the PARTIAL kernel so we finally profile the hot kernel.
    attnloss_pace_kernel<<<1, 32>>>();
    attnloss_partial_kernel<<<ROWS, NTHR>>>(
        x, attn, noise, mask,
        pB1, pT1, pC1, pP1,
        pB2, pT2, pC2, pP2,
        pB3, pT3, pC3, pP3);
    attnloss_final_kernel<<<1, FTHR>>>((float*)d_out);
    attnloss_pace_kernel<<<1, 32>>>();
}